// round 9
// baseline (speedup 1.0000x reference)
#include <cuda_runtime.h>
#include <cstdint>

// GestureClassifier: 2 stacks x 5-layer LSTM (H=32, B=16384, T=20) + FC(1280->128 relu ->5)
// Strategy: one thread per batch element, f32x2 packed FMAs (reduction-dim packing),
// weights broadcast from shared, inter-layer handoff via [t][h][B] global scratch.

#define BB 16384
#define TT 20
#define HH 32

typedef unsigned long long ull;

static __device__ float d_scr[2][2][(size_t)TT * HH * BB];       // [stack][parity][t*32+h][b]
static __device__ float d_fcT[(size_t)2 * TT * HH * BB];         // [k=0..1279][b]  (A^T for FC)
static __device__ float d_wt[1280 * 128];                        // fc1_w transposed [k][o]

// ---------------- f32x2 helpers ----------------
__device__ __forceinline__ ull pk2(float lo, float hi) {
    ull r; asm("mov.b64 %0, {%1, %2};" : "=l"(r) : "f"(lo), "f"(hi)); return r;
}
__device__ __forceinline__ void up2(ull v, float& lo, float& hi) {
    asm("mov.b64 {%0, %1}, %2;" : "=f"(lo), "=f"(hi) : "l"(v));
}
__device__ __forceinline__ ull fma2(ull a, ull b, ull c) {
    ull d; asm("fma.rn.f32x2 %0, %1, %2, %3;" : "=l"(d) : "l"(a), "l"(b), "l"(c)); return d;
}
__device__ __forceinline__ ull add2(ull a, ull b) {
    ull d; asm("add.rn.f32x2 %0, %1, %2;" : "=l"(d) : "l"(a), "l"(b)); return d;
}

__device__ __forceinline__ float sigf(float x) {
    return __fdividef(1.f, 1.f + __expf(-x));
}
__device__ __forceinline__ float tanhfast(float x) {
    return __fdividef(2.f, 1.f + __expf(-2.f * x)) - 1.f;
}

// ---------------- LSTM ----------------
// gate preactivation for one gate row: bias + Wih_row . x + Whh_row . h
// NXP = number of f32x2 pairs of the input vector (16 for H=32 input, 2 for padded D=3)
template <int NXP>
__device__ __forceinline__ float gate_dot(const float* wi_row, const float* wh_row,
                                          const ull* xv, const ull* hv, float bias) {
    const ulonglong2* wi = reinterpret_cast<const ulonglong2*>(wi_row);
    const ulonglong2* wh = reinterpret_cast<const ulonglong2*>(wh_row);
    ull a0 = 0, a1 = 0, a2 = 0, a3 = 0;
#pragma unroll
    for (int q = 0; q < NXP / 2; q++) {
        ulonglong2 w = wi[q];
        a0 = fma2(w.x, xv[2 * q], a0);
        a1 = fma2(w.y, xv[2 * q + 1], a1);
    }
#pragma unroll
    for (int q = 0; q < 8; q++) {
        ulonglong2 w = wh[q];
        a2 = fma2(w.x, hv[2 * q], a2);
        a3 = fma2(w.y, hv[2 * q + 1], a3);
    }
    ull s = add2(add2(a0, a2), add2(a1, a3));
    float lo, hi; up2(s, lo, hi);
    return bias + lo + hi;
}

// One LSTM layer for one batch element.
//  FIRST: x from raw input [b][t][3];  else: x from src[t*32+k][b]
//  dst[t*32+j][b] receives h; h for step t is reloaded from dst[t-1] (same thread).
template <int NXP, bool FIRST>
__device__ __forceinline__ void run_layer(int b, const float* __restrict__ in3,
                                          const float* __restrict__ src,
                                          float* __restrict__ dst,
                                          const float* sWi, const float* sWh,
                                          const float* sB, float* csrow) {
    ull xv[16], hv[16];
#pragma unroll
    for (int p = 0; p < 16; p++) { xv[p] = 0ull; hv[p] = 0ull; }
#pragma unroll
    for (int j = 0; j < 32; j++) csrow[j * 64] = 0.f;

#pragma unroll 1
    for (int t = 0; t < TT; t++) {
        if constexpr (FIRST) {
            const float* p = in3 + ((size_t)b * TT + t) * 3;
            xv[0] = pk2(p[0], p[1]);
            xv[1] = pk2(p[2], 0.f);
        } else {
            const float* s0 = src + (size_t)t * HH * BB + b;
#pragma unroll
            for (int p = 0; p < 16; p++)
                xv[p] = pk2(s0[(size_t)(2 * p) * BB], s0[(size_t)(2 * p + 1) * BB]);
        }
        if (t > 0) {
            const float* h0 = dst + (size_t)(t - 1) * HH * BB + b;
#pragma unroll
            for (int p = 0; p < 16; p++)
                hv[p] = pk2(h0[(size_t)(2 * p) * BB], h0[(size_t)(2 * p + 1) * BB]);
        }
        float* o0 = dst + (size_t)t * HH * BB + b;
#pragma unroll 2
        for (int j = 0; j < 32; j++) {
            float gi = gate_dot<NXP>(sWi + j * 32,          sWh + j * 32,          xv, hv, sB[j]);
            float gf = gate_dot<NXP>(sWi + (32 + j) * 32,   sWh + (32 + j) * 32,   xv, hv, sB[32 + j]);
            float gg = gate_dot<NXP>(sWi + (64 + j) * 32,   sWh + (64 + j) * 32,   xv, hv, sB[64 + j]);
            float go = gate_dot<NXP>(sWi + (96 + j) * 32,   sWh + (96 + j) * 32,   xv, hv, sB[96 + j]);
            float ig = sigf(gi);
            float fg = sigf(gf);
            float gv = tanhfast(gg);
            float og = sigf(go);
            float c = fg * csrow[j * 64] + ig * gv;
            csrow[j * 64] = c;
            o0[(size_t)j * BB] = og * tanhfast(c);
        }
    }
}

__global__ void __launch_bounds__(64) lstm_kernel(
    const float* __restrict__ accel, const float* __restrict__ gyro,
    const float* __restrict__ aWih0, const float* __restrict__ aWihR,
    const float* __restrict__ aWhh,  const float* __restrict__ abih, const float* __restrict__ abhh,
    const float* __restrict__ gWih0, const float* __restrict__ gWihR,
    const float* __restrict__ gWhh,  const float* __restrict__ gbih, const float* __restrict__ gbhh) {
    const int stack = blockIdx.y;
    const int tid = threadIdx.x;
    const int b = blockIdx.x * 64 + tid;

    const float* inp  = stack ? gyro  : accel;
    const float* Wih0 = stack ? gWih0 : aWih0;
    const float* WihR = stack ? gWihR : aWihR;
    const float* Whh  = stack ? gWhh  : aWhh;
    const float* bih  = stack ? gbih  : abih;
    const float* bhh  = stack ? gbhh  : abhh;

    __shared__ __align__(16) float sWi[128 * 32];
    __shared__ __align__(16) float sWh[128 * 32];
    __shared__ float sB[128];
    __shared__ float cs[32 * 64];
    float* csrow = cs + tid;

#pragma unroll 1
    for (int l = 0; l < 5; l++) {
        __syncthreads();
        if (l == 0) {
            for (int idx = tid; idx < 128 * 32; idx += 64) {
                int k = idx & 31;
                sWi[idx] = (k < 3) ? Wih0[(idx >> 5) * 3 + k] : 0.f;
            }
        } else {
            const float* w = WihR + (size_t)(l - 1) * 4096;
            for (int idx = tid; idx < 4096; idx += 64) sWi[idx] = w[idx];
        }
        {
            const float* w = Whh + (size_t)l * 4096;
            for (int idx = tid; idx < 4096; idx += 64) sWh[idx] = w[idx];
        }
        for (int idx = tid; idx < 128; idx += 64) sB[idx] = bih[l * 128 + idx] + bhh[l * 128 + idx];
        __syncthreads();

        float* dst = (l == 4) ? (d_fcT + (size_t)stack * TT * HH * BB)
                              : d_scr[stack][l & 1];
        if (l == 0)
            run_layer<2, true>(b, inp, nullptr, dst, sWi, sWh, sB, csrow);
        else
            run_layer<16, false>(b, nullptr, d_scr[stack][(l - 1) & 1], dst, sWi, sWh, sB, csrow);
    }
}

// ---------------- FC head ----------------
__global__ void transpose_w(const float* __restrict__ w) {
    int idx = blockIdx.x * 256 + threadIdx.x;  // 1280*128 exact
    int k = idx >> 7, o = idx & 127;
    d_wt[idx] = w[o * 1280 + k];
}

// out[b][0..4] = fc2( relu( fc1(x_flat[b]) ) ), x_flat read from d_fcT ([k][b]).
__global__ void __launch_bounds__(256) fc_kernel(
    const float* __restrict__ fc1b, const float* __restrict__ fc2w,
    const float* __restrict__ fc2b, float* __restrict__ out) {
    __shared__ __align__(16) float As[16][64];    // A^T tile: [k][b]
    __shared__ __align__(16) float Ws[16 * 128];  // W^T tile: [k][o]
    __shared__ float H1[64][132];                 // relu(fc1) staging

    const int tid = threadIdx.x;
    const int b0 = blockIdx.x * 64;
    const int mi = tid & 15;   // b micro-group (4 rows)
    const int ni = tid >> 4;   // o micro-group (8 cols)

    ull acc[4][4];
#pragma unroll
    for (int i = 0; i < 4; i++)
#pragma unroll
        for (int p = 0; p < 4; p++) acc[i][p] = 0ull;

    const int akl = tid >> 4;
    const int ac4 = (tid & 15) * 4;

#pragma unroll 1
    for (int k0 = 0; k0 < 1280; k0 += 16) {
        __syncthreads();
        *(float4*)&As[akl][ac4] = *(const float4*)&d_fcT[(size_t)(k0 + akl) * BB + b0 + ac4];
        *(float4*)&Ws[tid * 4]        = *(const float4*)&d_wt[k0 * 128 + tid * 4];
        *(float4*)&Ws[1024 + tid * 4] = *(const float4*)&d_wt[k0 * 128 + 1024 + tid * 4];
        __syncthreads();
#pragma unroll
        for (int kl = 0; kl < 16; kl++) {
            float4 av = *(const float4*)&As[kl][mi * 4];
            ull ad0 = pk2(av.x, av.x), ad1 = pk2(av.y, av.y);
            ull ad2 = pk2(av.z, av.z), ad3 = pk2(av.w, av.w);
            const ulonglong2* wp = (const ulonglong2*)&Ws[kl * 128 + ni * 8];
            ulonglong2 w01 = wp[0], w23 = wp[1];
            acc[0][0] = fma2(ad0, w01.x, acc[0][0]); acc[0][1] = fma2(ad0, w01.y, acc[0][1]);
            acc[0][2] = fma2(ad0, w23.x, acc[0][2]); acc[0][3] = fma2(ad0, w23.y, acc[0][3]);
            acc[1][0] = fma2(ad1, w01.x, acc[1][0]); acc[1][1] = fma2(ad1, w01.y, acc[1][1]);
            acc[1][2] = fma2(ad1, w23.x, acc[1][2]); acc[1][3] = fma2(ad1, w23.y, acc[1][3]);
            acc[2][0] = fma2(ad2, w01.x, acc[2][0]); acc[2][1] = fma2(ad2, w01.y, acc[2][1]);
            acc[2][2] = fma2(ad2, w23.x, acc[2][2]); acc[2][3] = fma2(ad2, w23.y, acc[2][3]);
            acc[3][0] = fma2(ad3, w01.x, acc[3][0]); acc[3][1] = fma2(ad3, w01.y, acc[3][1]);
            acc[3][2] = fma2(ad3, w23.x, acc[3][2]); acc[3][3] = fma2(ad3, w23.y, acc[3][3]);
        }
    }
    __syncthreads();
#pragma unroll
    for (int i = 0; i < 4; i++) {
        int bl = mi * 4 + i;
#pragma unroll
        for (int p = 0; p < 4; p++) {
            int o = ni * 8 + 2 * p;
            float lo, hi; up2(acc[i][p], lo, hi);
            H1[bl][o]     = fmaxf(lo + fc1b[o], 0.f);
            H1[bl][o + 1] = fmaxf(hi + fc1b[o + 1], 0.f);
        }
    }
    __syncthreads();
    for (int idx = tid; idx < 320; idx += 256) {
        int bl = idx / 5, oo = idx - bl * 5;
        const float* w = fc2w + oo * 128;
        float s = fc2b[oo];
#pragma unroll 4
        for (int k = 0; k < 128; k++) s += H1[bl][k] * w[k];
        out[(size_t)(b0 + bl) * 5 + oo] = s;
    }
}

extern "C" void kernel_launch(void* const* d_in, const int* in_sizes, int n_in,
                              void* d_out, int out_size) {
    const float* accel = (const float*)d_in[0];
    const float* gyro  = (const float*)d_in[1];
    const float* aWih0 = (const float*)d_in[2];
    const float* aWihR = (const float*)d_in[3];
    const float* aWhh  = (const float*)d_in[4];
    const float* abih  = (const float*)d_in[5];
    const float* abhh  = (const float*)d_in[6];
    const float* gWih0 = (const float*)d_in[7];
    const float* gWihR = (const float*)d_in[8];
    const float* gWhh  = (const float*)d_in[9];
    const float* gbih  = (const float*)d_in[10];
    const float* gbhh  = (const float*)d_in[11];
    const float* fc1w  = (const float*)d_in[12];
    const float* fc1b  = (const float*)d_in[13];
    const float* fc2w  = (const float*)d_in[14];
    const float* fc2b  = (const float*)d_in[15];

    transpose_w<<<640, 256>>>(fc1w);

    dim3 grid(BB / 64, 2);
    lstm_kernel<<<grid, 64>>>(accel, gyro, aWih0, aWihR, aWhh, abih, abhh,
                              gWih0, gWihR, gWhh, gbih, gbhh);

    fc_kernel<<<BB / 64, 256>>>(fc1b, fc2w, fc2b, (float*)d_out);
}

// round 10
// speedup vs baseline: 1.0021x; 1.0021x over previous
#include <cuda_runtime.h>
#include <cstdint>

// GestureClassifier: 2 stacks x 5-layer LSTM (H=32, B=16384, T=20) + FC(1280->128 relu ->5)
// Strategy: one thread per batch element, f32x2 packed FMAs (reduction-dim packing),
// weights broadcast from shared, inter-layer handoff via [t][h][B] global scratch.

#define BB 16384
#define TT 20
#define HH 32

typedef unsigned long long ull;

static __device__ float d_scr[2][2][(size_t)TT * HH * BB];       // [stack][parity][t*32+h][b]
static __device__ float d_fcT[(size_t)2 * TT * HH * BB];         // [k=0..1279][b]  (A^T for FC)
static __device__ float d_wt[1280 * 128];                        // fc1_w transposed [k][o]

// ---------------- f32x2 helpers ----------------
__device__ __forceinline__ ull pk2(float lo, float hi) {
    ull r; asm("mov.b64 %0, {%1, %2};" : "=l"(r) : "f"(lo), "f"(hi)); return r;
}
__device__ __forceinline__ void up2(ull v, float& lo, float& hi) {
    asm("mov.b64 {%0, %1}, %2;" : "=f"(lo), "=f"(hi) : "l"(v));
}
__device__ __forceinline__ ull fma2(ull a, ull b, ull c) {
    ull d; asm("fma.rn.f32x2 %0, %1, %2, %3;" : "=l"(d) : "l"(a), "l"(b), "l"(c)); return d;
}
__device__ __forceinline__ ull add2(ull a, ull b) {
    ull d; asm("add.rn.f32x2 %0, %1, %2;" : "=l"(d) : "l"(a), "l"(b)); return d;
}

__device__ __forceinline__ float sigf(float x) {
    return __fdividef(1.f, 1.f + __expf(-x));
}
__device__ __forceinline__ float tanhfast(float x) {
    return __fdividef(2.f, 1.f + __expf(-2.f * x)) - 1.f;
}

// ---------------- LSTM ----------------
// gate preactivation for one gate row: bias + Wih_row . x + Whh_row . h
// NXP = number of f32x2 pairs of the input vector (16 for H=32 input, 2 for padded D=3)
template <int NXP>
__device__ __forceinline__ float gate_dot(const float* wi_row, const float* wh_row,
                                          const ull* xv, const ull* hv, float bias) {
    const ulonglong2* wi = reinterpret_cast<const ulonglong2*>(wi_row);
    const ulonglong2* wh = reinterpret_cast<const ulonglong2*>(wh_row);
    ull a0 = 0, a1 = 0, a2 = 0, a3 = 0;
#pragma unroll
    for (int q = 0; q < NXP / 2; q++) {
        ulonglong2 w = wi[q];
        a0 = fma2(w.x, xv[2 * q], a0);
        a1 = fma2(w.y, xv[2 * q + 1], a1);
    }
#pragma unroll
    for (int q = 0; q < 8; q++) {
        ulonglong2 w = wh[q];
        a2 = fma2(w.x, hv[2 * q], a2);
        a3 = fma2(w.y, hv[2 * q + 1], a3);
    }
    ull s = add2(add2(a0, a2), add2(a1, a3));
    float lo, hi; up2(s, lo, hi);
    return bias + lo + hi;
}

// One LSTM layer for one batch element.
//  FIRST: x from raw input [b][t][3];  else: x from src[t*32+k][b]
//  dst[t*32+j][b] receives h; h for step t is reloaded from dst[t-1] (same thread).
template <int NXP, bool FIRST>
__device__ __forceinline__ void run_layer(int b, const float* __restrict__ in3,
                                          const float* __restrict__ src,
                                          float* __restrict__ dst,
                                          const float* sWi, const float* sWh,
                                          const float* sB, float* csrow) {
    ull xv[16], hv[16];
#pragma unroll
    for (int p = 0; p < 16; p++) { xv[p] = 0ull; hv[p] = 0ull; }
#pragma unroll
    for (int j = 0; j < 32; j++) csrow[j * 64] = 0.f;

#pragma unroll 1
    for (int t = 0; t < TT; t++) {
        if constexpr (FIRST) {
            const float* p = in3 + ((size_t)b * TT + t) * 3;
            xv[0] = pk2(p[0], p[1]);
            xv[1] = pk2(p[2], 0.f);
        } else {
            const float* s0 = src + (size_t)t * HH * BB + b;
#pragma unroll
            for (int p = 0; p < 16; p++)
                xv[p] = pk2(s0[(size_t)(2 * p) * BB], s0[(size_t)(2 * p + 1) * BB]);
        }
        if (t > 0) {
            const float* h0 = dst + (size_t)(t - 1) * HH * BB + b;
#pragma unroll
            for (int p = 0; p < 16; p++)
                hv[p] = pk2(h0[(size_t)(2 * p) * BB], h0[(size_t)(2 * p + 1) * BB]);
        }
        float* o0 = dst + (size_t)t * HH * BB + b;
#pragma unroll 2
        for (int j = 0; j < 32; j++) {
            float gi = gate_dot<NXP>(sWi + j * 32,          sWh + j * 32,          xv, hv, sB[j]);
            float gf = gate_dot<NXP>(sWi + (32 + j) * 32,   sWh + (32 + j) * 32,   xv, hv, sB[32 + j]);
            float gg = gate_dot<NXP>(sWi + (64 + j) * 32,   sWh + (64 + j) * 32,   xv, hv, sB[64 + j]);
            float go = gate_dot<NXP>(sWi + (96 + j) * 32,   sWh + (96 + j) * 32,   xv, hv, sB[96 + j]);
            float ig = sigf(gi);
            float fg = sigf(gf);
            float gv = tanhfast(gg);
            float og = sigf(go);
            float c = fg * csrow[j * 64] + ig * gv;
            csrow[j * 64] = c;
            o0[(size_t)j * BB] = og * tanhfast(c);
        }
    }
}

__global__ void __launch_bounds__(64) lstm_kernel(
    const float* __restrict__ accel, const float* __restrict__ gyro,
    const float* __restrict__ aWih0, const float* __restrict__ aWihR,
    const float* __restrict__ aWhh,  const float* __restrict__ abih, const float* __restrict__ abhh,
    const float* __restrict__ gWih0, const float* __restrict__ gWihR,
    const float* __restrict__ gWhh,  const float* __restrict__ gbih, const float* __restrict__ gbhh) {
    const int stack = blockIdx.y;
    const int tid = threadIdx.x;
    const int b = blockIdx.x * 64 + tid;

    const float* inp  = stack ? gyro  : accel;
    const float* Wih0 = stack ? gWih0 : aWih0;
    const float* WihR = stack ? gWihR : aWihR;
    const float* Whh  = stack ? gWhh  : aWhh;
    const float* bih  = stack ? gbih  : abih;
    const float* bhh  = stack ? gbhh  : abhh;

    __shared__ __align__(16) float sWi[128 * 32];
    __shared__ __align__(16) float sWh[128 * 32];
    __shared__ float sB[128];
    __shared__ float cs[32 * 64];
    float* csrow = cs + tid;

#pragma unroll 1
    for (int l = 0; l < 5; l++) {
        __syncthreads();
        if (l == 0) {
            for (int idx = tid; idx < 128 * 32; idx += 64) {
                int k = idx & 31;
                sWi[idx] = (k < 3) ? Wih0[(idx >> 5) * 3 + k] : 0.f;
            }
        } else {
            const float* w = WihR + (size_t)(l - 1) * 4096;
            for (int idx = tid; idx < 4096; idx += 64) sWi[idx] = w[idx];
        }
        {
            const float* w = Whh + (size_t)l * 4096;
            for (int idx = tid; idx < 4096; idx += 64) sWh[idx] = w[idx];
        }
        for (int idx = tid; idx < 128; idx += 64) sB[idx] = bih[l * 128 + idx] + bhh[l * 128 + idx];
        __syncthreads();

        float* dst = (l == 4) ? (d_fcT + (size_t)stack * TT * HH * BB)
                              : d_scr[stack][l & 1];
        if (l == 0)
            run_layer<2, true>(b, inp, nullptr, dst, sWi, sWh, sB, csrow);
        else
            run_layer<16, false>(b, nullptr, d_scr[stack][(l - 1) & 1], dst, sWi, sWh, sB, csrow);
    }
}

// ---------------- FC head ----------------
__global__ void transpose_w(const float* __restrict__ w) {
    int idx = blockIdx.x * 256 + threadIdx.x;  // 1280*128 exact
    int k = idx >> 7, o = idx & 127;
    d_wt[idx] = w[o * 1280 + k];
}

// out[b][0..4] = fc2( relu( fc1(x_flat[b]) ) ), x_flat read from d_fcT ([k][b]).
__global__ void __launch_bounds__(256) fc_kernel(
    const float* __restrict__ fc1b, const float* __restrict__ fc2w,
    const float* __restrict__ fc2b, float* __restrict__ out) {
    __shared__ __align__(16) float As[16][64];    // A^T tile: [k][b]
    __shared__ __align__(16) float Ws[16 * 128];  // W^T tile: [k][o]
    __shared__ float H1[64][132];                 // relu(fc1) staging

    const int tid = threadIdx.x;
    const int b0 = blockIdx.x * 64;
    const int mi = tid & 15;   // b micro-group (4 rows)
    const int ni = tid >> 4;   // o micro-group (8 cols)

    ull acc[4][4];
#pragma unroll
    for (int i = 0; i < 4; i++)
#pragma unroll
        for (int p = 0; p < 4; p++) acc[i][p] = 0ull;

    const int akl = tid >> 4;
    const int ac4 = (tid & 15) * 4;

#pragma unroll 1
    for (int k0 = 0; k0 < 1280; k0 += 16) {
        __syncthreads();
        *(float4*)&As[akl][ac4] = *(const float4*)&d_fcT[(size_t)(k0 + akl) * BB + b0 + ac4];
        *(float4*)&Ws[tid * 4]        = *(const float4*)&d_wt[k0 * 128 + tid * 4];
        *(float4*)&Ws[1024 + tid * 4] = *(const float4*)&d_wt[k0 * 128 + 1024 + tid * 4];
        __syncthreads();
#pragma unroll
        for (int kl = 0; kl < 16; kl++) {
            float4 av = *(const float4*)&As[kl][mi * 4];
            ull ad0 = pk2(av.x, av.x), ad1 = pk2(av.y, av.y);
            ull ad2 = pk2(av.z, av.z), ad3 = pk2(av.w, av.w);
            const ulonglong2* wp = (const ulonglong2*)&Ws[kl * 128 + ni * 8];
            ulonglong2 w01 = wp[0], w23 = wp[1];
            acc[0][0] = fma2(ad0, w01.x, acc[0][0]); acc[0][1] = fma2(ad0, w01.y, acc[0][1]);
            acc[0][2] = fma2(ad0, w23.x, acc[0][2]); acc[0][3] = fma2(ad0, w23.y, acc[0][3]);
            acc[1][0] = fma2(ad1, w01.x, acc[1][0]); acc[1][1] = fma2(ad1, w01.y, acc[1][1]);
            acc[1][2] = fma2(ad1, w23.x, acc[1][2]); acc[1][3] = fma2(ad1, w23.y, acc[1][3]);
            acc[2][0] = fma2(ad2, w01.x, acc[2][0]); acc[2][1] = fma2(ad2, w01.y, acc[2][1]);
            acc[2][2] = fma2(ad2, w23.x, acc[2][2]); acc[2][3] = fma2(ad2, w23.y, acc[2][3]);
            acc[3][0] = fma2(ad3, w01.x, acc[3][0]); acc[3][1] = fma2(ad3, w01.y, acc[3][1]);
            acc[3][2] = fma2(ad3, w23.x, acc[3][2]); acc[3][3] = fma2(ad3, w23.y, acc[3][3]);
        }
    }
    __syncthreads();
#pragma unroll
    for (int i = 0; i < 4; i++) {
        int bl = mi * 4 + i;
#pragma unroll
        for (int p = 0; p < 4; p++) {
            int o = ni * 8 + 2 * p;
            float lo, hi; up2(acc[i][p], lo, hi);
            H1[bl][o]     = fmaxf(lo + fc1b[o], 0.f);
            H1[bl][o + 1] = fmaxf(hi + fc1b[o + 1], 0.f);
        }
    }
    __syncthreads();
    for (int idx = tid; idx < 320; idx += 256) {
        int bl = idx / 5, oo = idx - bl * 5;
        const float* w = fc2w + oo * 128;
        float s = fc2b[oo];
#pragma unroll 4
        for (int k = 0; k < 128; k++) s += H1[bl][k] * w[k];
        out[(size_t)(b0 + bl) * 5 + oo] = s;
    }
}

extern "C" void kernel_launch(void* const* d_in, const int* in_sizes, int n_in,
                              void* d_out, int out_size) {
    const float* accel = (const float*)d_in[0];
    const float* gyro  = (const float*)d_in[1];
    const float* aWih0 = (const float*)d_in[2];
    const float* aWihR = (const float*)d_in[3];
    const float* aWhh  = (const float*)d_in[4];
    const float* abih  = (const float*)d_in[5];
    const float* abhh  = (const float*)d_in[6];
    const float* gWih0 = (const float*)d_in[7];
    const float* gWihR = (const float*)d_in[8];
    const float* gWhh  = (const float*)d_in[9];
    const float* gbih  = (const float*)d_in[10];
    const float* gbhh  = (const float*)d_in[11];
    const float* fc1w  = (const float*)d_in[12];
    const float* fc1b  = (const float*)d_in[13];
    const float* fc2w  = (const float*)d_in[14];
    const float* fc2b  = (const float*)d_in[15];

    transpose_w<<<640, 256>>>(fc1w);

    dim3 grid(BB / 64, 2);
    lstm_kernel<<<grid, 64>>>(accel, gyro, aWih0, aWihR, aWhh, abih, abhh,
                              gWih0, gWihR, gWhh, gbih, gbhh);

    fc_kernel<<<BB / 64, 256>>>(fc1b, fc2w, fc2b, (float*)d_out);
}

// round 11
// speedup vs baseline: 1.0105x; 1.0083x over previous
#include <cuda_runtime.h>
#include <cstdint>

// GestureClassifier: 2 stacks x 5-layer LSTM (H=32, B=16384, T=20) + FC(1280->128 relu ->5)
// v2: two warps per 32 batch elements (j-split), h exchanged via smem (no global
// round-trip), c in smem, 2048 warps (single wave), f32x2 packed FMAs, weights
// broadcast from shared (same-address within each warp -> conflict-free).

#define BB 16384
#define TT 20
#define HH 32

typedef unsigned long long ull;

static __device__ float d_scr[2][2][(size_t)TT * HH * BB];       // [stack][parity][t*32+h][b]
static __device__ float d_fcT[(size_t)2 * TT * HH * BB];         // [k=0..1279][b]  (A^T for FC)
static __device__ float d_wt[1280 * 128];                        // fc1_w transposed [k][o]

// ---------------- f32x2 helpers ----------------
__device__ __forceinline__ ull pk2(float lo, float hi) {
    ull r; asm("mov.b64 %0, {%1, %2};" : "=l"(r) : "f"(lo), "f"(hi)); return r;
}
__device__ __forceinline__ void up2(ull v, float& lo, float& hi) {
    asm("mov.b64 {%0, %1}, %2;" : "=f"(lo), "=f"(hi) : "l"(v));
}
__device__ __forceinline__ ull fma2(ull a, ull b, ull c) {
    ull d; asm("fma.rn.f32x2 %0, %1, %2, %3;" : "=l"(d) : "l"(a), "l"(b), "l"(c)); return d;
}
__device__ __forceinline__ ull add2(ull a, ull b) {
    ull d; asm("add.rn.f32x2 %0, %1, %2;" : "=l"(d) : "l"(a), "l"(b)); return d;
}

__device__ __forceinline__ float sigf(float x) {
    return __fdividef(1.f, 1.f + __expf(-x));
}
__device__ __forceinline__ float tanhfast(float x) {
    return __fdividef(2.f, 1.f + __expf(-2.f * x)) - 1.f;
}

// ---------------- LSTM ----------------
// gate preactivation for one gate row: bias + Wih_row . x + Whh_row . h
// NXP = number of f32x2 pairs of the input vector (16 for H=32 input, 2 for padded D=3)
template <int NXP>
__device__ __forceinline__ float gate_dot(const float* wi_row, const float* wh_row,
                                          const ull* xv, const ull* hv, float bias) {
    const ulonglong2* wi = reinterpret_cast<const ulonglong2*>(wi_row);
    const ulonglong2* wh = reinterpret_cast<const ulonglong2*>(wh_row);
    ull a0 = pk2(bias, 0.f), a1 = 0, a2 = 0, a3 = 0;
#pragma unroll
    for (int q = 0; q < NXP / 2; q++) {
        ulonglong2 w = wi[q];
        a0 = fma2(w.x, xv[2 * q], a0);
        a1 = fma2(w.y, xv[2 * q + 1], a1);
    }
#pragma unroll
    for (int q = 0; q < 8; q++) {
        ulonglong2 w = wh[q];
        a2 = fma2(w.x, hv[2 * q], a2);
        a3 = fma2(w.y, hv[2 * q + 1], a3);
    }
    ull s = add2(add2(a0, a2), add2(a1, a3));
    float lo, hi; up2(s, lo, hi);
    return lo + hi;
}

// One LSTM layer; this thread owns 16 gate rows (jb..jb+15) of element b.
// h for the NEXT step comes from smem hxp (both warps of the team contribute).
template <int NXP, bool FIRST>
__device__ __forceinline__ void run_layer(
    int tid, int e, int jb, int b,
    const float* __restrict__ in3, const float* __restrict__ src,
    float* __restrict__ dst,
    const float* sWi, const float* sWh, const float* sB,
    float* cb, ull* hxp)
{
    ull xv[16], hv[16];
#pragma unroll
    for (int p = 0; p < 16; p++) hv[p] = 0ull;
#pragma unroll
    for (int p = 0; p < NXP; p++) xv[p] = 0ull;
#pragma unroll
    for (int jj = 0; jj < 16; jj++) cb[jj * 128 + tid] = 0.f;

#pragma unroll 1
    for (int t = 0; t < TT; t++) {
        if constexpr (FIRST) {
            const float* p = in3 + ((size_t)b * TT + t) * 3;
            xv[0] = pk2(p[0], p[1]);
            xv[1] = pk2(p[2], 0.f);
        } else {
            const float* s0 = src + (size_t)t * HH * BB + b;
#pragma unroll
            for (int p = 0; p < 16; p++)
                xv[p] = pk2(s0[(size_t)(2 * p) * BB], s0[(size_t)(2 * p + 1) * BB]);
        }
        if (t > 0) {
#pragma unroll
            for (int p = 0; p < 16; p++) hv[p] = hxp[p * 64 + e];
        }
        __syncthreads();   // all hv reads done before hxp is overwritten below

        float* orow = dst + (size_t)t * HH * BB + b;
#pragma unroll 2
        for (int jp = 0; jp < 8; jp++) {
            const int j0 = jb + 2 * jp;
            const int j1 = j0 + 1;
            float gi0 = gate_dot<NXP>(sWi + j0 * 32,          sWh + j0 * 32,          xv, hv, sB[j0]);
            float gf0 = gate_dot<NXP>(sWi + (j0 + 32) * 32,   sWh + (j0 + 32) * 32,   xv, hv, sB[j0 + 32]);
            float gg0 = gate_dot<NXP>(sWi + (j0 + 64) * 32,   sWh + (j0 + 64) * 32,   xv, hv, sB[j0 + 64]);
            float go0 = gate_dot<NXP>(sWi + (j0 + 96) * 32,   sWh + (j0 + 96) * 32,   xv, hv, sB[j0 + 96]);
            float gi1 = gate_dot<NXP>(sWi + j1 * 32,          sWh + j1 * 32,          xv, hv, sB[j1]);
            float gf1 = gate_dot<NXP>(sWi + (j1 + 32) * 32,   sWh + (j1 + 32) * 32,   xv, hv, sB[j1 + 32]);
            float gg1 = gate_dot<NXP>(sWi + (j1 + 64) * 32,   sWh + (j1 + 64) * 32,   xv, hv, sB[j1 + 64]);
            float go1 = gate_dot<NXP>(sWi + (j1 + 96) * 32,   sWh + (j1 + 96) * 32,   xv, hv, sB[j1 + 96]);

            float c0 = sigf(gf0) * cb[(2 * jp) * 128 + tid]     + sigf(gi0) * tanhfast(gg0);
            float c1 = sigf(gf1) * cb[(2 * jp + 1) * 128 + tid] + sigf(gi1) * tanhfast(gg1);
            cb[(2 * jp) * 128 + tid]     = c0;
            cb[(2 * jp + 1) * 128 + tid] = c1;
            float h0 = sigf(go0) * tanhfast(c0);
            float h1 = sigf(go1) * tanhfast(c1);

            hxp[(jb / 2 + jp) * 64 + e] = pk2(h0, h1);
            orow[(size_t)j0 * BB] = h0;
            orow[(size_t)j1 * BB] = h1;
        }
        __syncthreads();   // hxp writes visible before next step's reads
    }
}

__global__ void __launch_bounds__(128, 4) lstm_kernel(
    const float* __restrict__ accel, const float* __restrict__ gyro,
    const float* __restrict__ aWih0, const float* __restrict__ aWihR,
    const float* __restrict__ aWhh,  const float* __restrict__ abih, const float* __restrict__ abhh,
    const float* __restrict__ gWih0, const float* __restrict__ gWihR,
    const float* __restrict__ gWhh,  const float* __restrict__ gbih, const float* __restrict__ gbhh) {
    extern __shared__ unsigned char smraw[];
    float* sWi = (float*)smraw;            // 4096 f
    float* sWh = sWi + 4096;               // 4096 f
    float* sB  = sWh + 4096;               // 128 f
    float* cb  = sB + 128;                 // cbuf [16][128]
    ull*  hxp  = (ull*)(cb + 16 * 128);    // [16 pairs][64 elems]

    const int stack = blockIdx.y;
    const int tid = threadIdx.x;
    const int wid = tid >> 5;
    const int lane = tid & 31;
    const int e = (wid >> 1) * 32 + lane;   // element within block [0,64)
    const int jb = (wid & 1) * 16;          // this warp's j-half
    const int b = blockIdx.x * 64 + e;

    const float* inp  = stack ? gyro  : accel;
    const float* Wih0 = stack ? gWih0 : aWih0;
    const float* WihR = stack ? gWihR : aWihR;
    const float* Whh  = stack ? gWhh  : aWhh;
    const float* bih  = stack ? gbih  : abih;
    const float* bhh  = stack ? gbhh  : abhh;

#pragma unroll 1
    for (int l = 0; l < 5; l++) {
        __syncthreads();
        if (l == 0) {
            for (int idx = tid; idx < 4096; idx += 128) {
                int k = idx & 31;
                sWi[idx] = (k < 3) ? Wih0[(idx >> 5) * 3 + k] : 0.f;
            }
        } else {
            const float* w = WihR + (size_t)(l - 1) * 4096;
            for (int idx = tid; idx < 4096; idx += 128) sWi[idx] = w[idx];
        }
        {
            const float* w = Whh + (size_t)l * 4096;
            for (int idx = tid; idx < 4096; idx += 128) sWh[idx] = w[idx];
        }
        sB[tid] = bih[l * 128 + tid] + bhh[l * 128 + tid];
        __syncthreads();

        float* dst = (l == 4) ? (d_fcT + (size_t)stack * TT * HH * BB)
                              : d_scr[stack][l & 1];
        if (l == 0)
            run_layer<2, true>(tid, e, jb, b, inp, nullptr, dst, sWi, sWh, sB, cb, hxp);
        else
            run_layer<16, false>(tid, e, jb, b, nullptr, d_scr[stack][(l - 1) & 1],
                                 dst, sWi, sWh, sB, cb, hxp);
    }
}

// ---------------- FC head ----------------
__global__ void transpose_w(const float* __restrict__ w) {
    int idx = blockIdx.x * 256 + threadIdx.x;  // 1280*128 exact
    int k = idx >> 7, o = idx & 127;
    d_wt[idx] = w[o * 1280 + k];
}

// out[b][0..4] = fc2( relu( fc1(x_flat[b]) ) ), x_flat read from d_fcT ([k][b]).
__global__ void __launch_bounds__(256) fc_kernel(
    const float* __restrict__ fc1b, const float* __restrict__ fc2w,
    const float* __restrict__ fc2b, float* __restrict__ out) {
    __shared__ __align__(16) float As[16][64];    // A^T tile: [k][b]
    __shared__ __align__(16) float Ws[16 * 128];  // W^T tile: [k][o]
    __shared__ float H1[64][132];                 // relu(fc1) staging

    const int tid = threadIdx.x;
    const int b0 = blockIdx.x * 64;
    const int mi = tid & 15;   // b micro-group (4 rows)
    const int ni = tid >> 4;   // o micro-group (8 cols)

    ull acc[4][4];
#pragma unroll
    for (int i = 0; i < 4; i++)
#pragma unroll
        for (int p = 0; p < 4; p++) acc[i][p] = 0ull;

    const int akl = tid >> 4;
    const int ac4 = (tid & 15) * 4;

#pragma unroll 1
    for (int k0 = 0; k0 < 1280; k0 += 16) {
        __syncthreads();
        *(float4*)&As[akl][ac4] = *(const float4*)&d_fcT[(size_t)(k0 + akl) * BB + b0 + ac4];
        *(float4*)&Ws[tid * 4]        = *(const float4*)&d_wt[k0 * 128 + tid * 4];
        *(float4*)&Ws[1024 + tid * 4] = *(const float4*)&d_wt[k0 * 128 + 1024 + tid * 4];
        __syncthreads();
#pragma unroll
        for (int kl = 0; kl < 16; kl++) {
            float4 av = *(const float4*)&As[kl][mi * 4];
            ull ad0 = pk2(av.x, av.x), ad1 = pk2(av.y, av.y);
            ull ad2 = pk2(av.z, av.z), ad3 = pk2(av.w, av.w);
            const ulonglong2* wp = (const ulonglong2*)&Ws[kl * 128 + ni * 8];
            ulonglong2 w01 = wp[0], w23 = wp[1];
            acc[0][0] = fma2(ad0, w01.x, acc[0][0]); acc[0][1] = fma2(ad0, w01.y, acc[0][1]);
            acc[0][2] = fma2(ad0, w23.x, acc[0][2]); acc[0][3] = fma2(ad0, w23.y, acc[0][3]);
            acc[1][0] = fma2(ad1, w01.x, acc[1][0]); acc[1][1] = fma2(ad1, w01.y, acc[1][1]);
            acc[1][2] = fma2(ad1, w23.x, acc[1][2]); acc[1][3] = fma2(ad1, w23.y, acc[1][3]);
            acc[2][0] = fma2(ad2, w01.x, acc[2][0]); acc[2][1] = fma2(ad2, w01.y, acc[2][1]);
            acc[2][2] = fma2(ad2, w23.x, acc[2][2]); acc[2][3] = fma2(ad2, w23.y, acc[2][3]);
            acc[3][0] = fma2(ad3, w01.x, acc[3][0]); acc[3][1] = fma2(ad3, w01.y, acc[3][1]);
            acc[3][2] = fma2(ad3, w23.x, acc[3][2]); acc[3][3] = fma2(ad3, w23.y, acc[3][3]);
        }
    }
    __syncthreads();
#pragma unroll
    for (int i = 0; i < 4; i++) {
        int bl = mi * 4 + i;
#pragma unroll
        for (int p = 0; p < 4; p++) {
            int o = ni * 8 + 2 * p;
            float lo, hi; up2(acc[i][p], lo, hi);
            H1[bl][o]     = fmaxf(lo + fc1b[o], 0.f);
            H1[bl][o + 1] = fmaxf(hi + fc1b[o + 1], 0.f);
        }
    }
    __syncthreads();
    for (int idx = tid; idx < 320; idx += 256) {
        int bl = idx / 5, oo = idx - bl * 5;
        const float* w = fc2w + oo * 128;
        float s = fc2b[oo];
#pragma unroll 4
        for (int k = 0; k < 128; k++) s += H1[bl][k] * w[k];
        out[(size_t)(b0 + bl) * 5 + oo] = s;
    }
}

extern "C" void kernel_launch(void* const* d_in, const int* in_sizes, int n_in,
                              void* d_out, int out_size) {
    const float* accel = (const float*)d_in[0];
    const float* gyro  = (const float*)d_in[1];
    const float* aWih0 = (const float*)d_in[2];
    const float* aWihR = (const float*)d_in[3];
    const float* aWhh  = (const float*)d_in[4];
    const float* abih  = (const float*)d_in[5];
    const float* abhh  = (const float*)d_in[6];
    const float* gWih0 = (const float*)d_in[7];
    const float* gWihR = (const float*)d_in[8];
    const float* gWhh  = (const float*)d_in[9];
    const float* gbih  = (const float*)d_in[10];
    const float* gbhh  = (const float*)d_in[11];
    const float* fc1w  = (const float*)d_in[12];
    const float* fc1b  = (const float*)d_in[13];
    const float* fc2w  = (const float*)d_in[14];
    const float* fc2b  = (const float*)d_in[15];

    const int lstm_smem = (4096 + 4096 + 128 + 16 * 128) * 4 + 16 * 64 * 8;  // 49664 B
    cudaFuncSetAttribute(lstm_kernel, cudaFuncAttributeMaxDynamicSharedMemorySize, lstm_smem);

    transpose_w<<<640, 256>>>(fc1w);

    dim3 grid(BB / 64, 2);
    lstm_kernel<<<grid, 128, lstm_smem>>>(accel, gyro, aWih0, aWihR, aWhh, abih, abhh,
                                          gWih0, gWihR, gWhh, gbih, gbhh);

    fc_kernel<<<BB / 64, 256>>>(fc1b, fc2w, fc2b, (float*)d_out);
}

// round 13
// speedup vs baseline: 1.9814x; 1.9609x over previous
#include <cuda_runtime.h>
#include <cuda_bf16.h>
#include <cstdint>

// GestureClassifier: 2 stacks x 5-layer LSTM (H=32, B=16384, T=20) + FC(1280->128 relu ->5)
// v4: warp-level mma.sync bf16 (m16n8k16) for the gate GEMM; 3-pass hi/lo bf16 split.
//  - CTA = 4 warps = 64 batch elements. Warp w owns gate columns j in [8w, 8w+8)
//    (n-tiles {w, w+4, w+8, w+12} -> all four gates i/f/g/o for its j-octet).
//  - Weights resident in registers as B-fragments (64 regs), reloaded per layer.
//  - Accumulator->A fragment identity: h computed by a thread is already in its
//    A-operand position; cross-warp exchange via 8KB smem frag-slot buffer.
//  - Inter-layer h via gmem in packed (bf16 hi|lo) frag-slot layout, staged via smem.

#define BB 16384
#define TT 20
#define NCTA 512   // 2 stacks * 256 teams of 64 elements

typedef unsigned long long ull;

static __device__ ull   d_xchg[(size_t)NCTA * 2 * TT * 1024];  // [cta][parity][t][slot]
static __device__ float d_fcT[(size_t)2 * TT * 32 * BB];       // [k=0..1279][b]
static __device__ float d_wt[1280 * 128];                      // fc1_w transposed [k][o]

// ---------------- helpers ----------------
__device__ __forceinline__ uint32_t pkbf(float lo, float hi) {   // lo -> low 16 bits
    uint32_t r; asm("cvt.rn.bf16x2.f32 %0, %1, %2;" : "=r"(r) : "f"(hi), "f"(lo)); return r;
}
__device__ __forceinline__ void split2(float x0, float x1, uint32_t& h, uint32_t& l) {
    h = pkbf(x0, x1);
    float h0 = __uint_as_float(h << 16);
    float h1 = __uint_as_float(h & 0xFFFF0000u);
    l = pkbf(x0 - h0, x1 - h1);
}
__device__ __forceinline__ void hmma(float* d, const uint32_t* a, const uint32_t* b) {
    asm("mma.sync.aligned.m16n8k16.row.col.f32.bf16.bf16.f32 "
        "{%0,%1,%2,%3}, {%4,%5,%6,%7}, {%8,%9}, {%0,%1,%2,%3};"
        : "+f"(d[0]), "+f"(d[1]), "+f"(d[2]), "+f"(d[3])
        : "r"(a[0]), "r"(a[1]), "r"(a[2]), "r"(a[3]), "r"(b[0]), "r"(b[1]));
}
__device__ __forceinline__ float sigf(float x) { return __fdividef(1.f, 1.f + __expf(-x)); }
__device__ __forceinline__ float tanhfast(float x) { return __fdividef(2.f, 1.f + __expf(-2.f * x)) - 1.f; }

// ---------------- fused 5-layer LSTM ----------------
__global__ void __launch_bounds__(128) lstm_mma_kernel(
    const float* __restrict__ accel, const float* __restrict__ gyro,
    const float* __restrict__ aWih0, const float* __restrict__ aWihR,
    const float* __restrict__ aWhh,  const float* __restrict__ abih, const float* __restrict__ abhh,
    const float* __restrict__ gWih0, const float* __restrict__ gWihR,
    const float* __restrict__ gWhh,  const float* __restrict__ gbih, const float* __restrict__ gbhh) {
    __shared__ ull hx[2][1024];   // in-layer h exchange, [t parity][slot]
    __shared__ ull xb[2][1024];   // staged x (prev-layer h), [t parity][slot]

    const int tid  = threadIdx.x;
    const int w    = tid >> 5;
    const int lane = tid & 31;
    const int r    = lane >> 2;   // fragment row group
    const int c    = lane & 3;    // fragment col/k group
    const int cta  = blockIdx.x;
    const int stack = cta >> 8;
    const int e0   = (cta & 255) * 64;

    const float* inp  = stack ? gyro  : accel;
    const float* Wih0 = stack ? gWih0 : aWih0;
    const float* WihR = stack ? gWihR : aWihR;
    const float* Whh  = stack ? gWhh  : aWhh;
    const float* bih  = stack ? gbih  : abih;
    const float* bhh  = stack ? gbhh  : abhh;

    uint32_t bH[4][4][2], bL[4][4][2];   // [gate-block][k-tile][k8-half]
    float bias[4][2];
    float cst[4][4];                     // c state [mtile][rh*2+p]

#pragma unroll 1
    for (int l = 0; l < 5; l++) {
        // ---- B fragments (weights) + bias into registers
#pragma unroll
        for (int gb = 0; gb < 4; gb++) {
            const int n = 32 * gb + 8 * w + r;   // gate row of W
#pragma unroll
            for (int kt = 0; kt < 4; kt++)
#pragma unroll
                for (int hf = 0; hf < 2; hf++) {
                    int k0 = 16 * kt + 8 * hf + 2 * c;
                    float w0, w1;
                    if (k0 < 32) {
                        if (l == 0) {
                            w0 = (k0 < 3) ? Wih0[n * 3 + k0] : 0.f;
                            w1 = (k0 + 1 < 3) ? Wih0[n * 3 + k0 + 1] : 0.f;
                        } else {
                            const float* p = WihR + (size_t)(l - 1) * 4096 + n * 32;
                            w0 = p[k0]; w1 = p[k0 + 1];
                        }
                    } else {
                        const float* p = Whh + (size_t)l * 4096 + n * 32 - 32;
                        w0 = p[k0]; w1 = p[k0 + 1];
                    }
                    split2(w0, w1, bH[gb][kt][hf], bL[gb][kt][hf]);
                }
            int jj = 32 * gb + 8 * w + 2 * c;
            bias[gb][0] = bih[l * 128 + jj]     + bhh[l * 128 + jj];
            bias[gb][1] = bih[l * 128 + jj + 1] + bhh[l * 128 + jj + 1];
        }
#pragma unroll
        for (int m = 0; m < 4; m++)
#pragma unroll
            for (int q = 0; q < 4; q++) cst[m][q] = 0.f;

        const ull* xsrc = d_xchg + (size_t)(cta * 2 + ((l - 1) & 1)) * TT * 1024;
        ull* xdst = (l < 4) ? (d_xchg + (size_t)(cta * 2 + (l & 1)) * TT * 1024) : nullptr;

#pragma unroll 1
        for (int t = 0; t < TT; t++) {
            if (l > 0) {   // cooperative stage of x(t) = prev-layer h, packed-frag layout
                const ull* s = xsrc + (size_t)t * 1024;
                ull* dsm = xb[t & 1];
#pragma unroll
                for (int q = 0; q < 8; q++) dsm[tid + 128 * q] = s[tid + 128 * q];
            }
            __syncthreads();   // xb ready; prev-step hx writes visible; prev readers done

#pragma unroll
            for (int m = 0; m < 4; m++) {
                uint32_t aH[4][4], aL[4][4];
                // ---- x chunks (k 0..31)
                if (l == 0) {
#pragma unroll
                    for (int rh = 0; rh < 2; rh++) {
                        uint32_t vh = 0, vl = 0;
                        int e = e0 + 16 * m + r + 8 * rh;
                        const float* px = inp + ((size_t)e * TT + t) * 3;
                        if (c == 0)      split2(px[0], px[1], vh, vl);
                        else if (c == 1) split2(px[2], 0.f,  vh, vl);
                        aH[0][rh] = vh; aL[0][rh] = vl;
                        aH[0][2 + rh] = 0; aL[0][2 + rh] = 0;
                        aH[1][rh] = 0; aL[1][rh] = 0;
                        aH[1][2 + rh] = 0; aL[1][2 + rh] = 0;
                    }
                } else {
#pragma unroll
                    for (int cn = 0; cn < 2; cn++)
#pragma unroll
                        for (int hf = 0; hf < 2; hf++) {
                            int pw = 2 * cn + hf;
#pragma unroll
                            for (int rh = 0; rh < 2; rh++) {
                                ull v = xb[t & 1][((pw * 4 + m) * 2 + rh) * 32 + lane];
                                aH[cn][hf * 2 + rh] = (uint32_t)v;
                                aL[cn][hf * 2 + rh] = (uint32_t)(v >> 32);
                            }
                        }
                }
                // ---- h chunks (k 32..63)
#pragma unroll
                for (int cn = 2; cn < 4; cn++)
#pragma unroll
                    for (int hf = 0; hf < 2; hf++) {
                        int pw = 2 * (cn - 2) + hf;
#pragma unroll
                        for (int rh = 0; rh < 2; rh++) {
                            ull v = (t == 0) ? 0ull
                                   : hx[t & 1][((pw * 4 + m) * 2 + rh) * 32 + lane];
                            aH[cn][hf * 2 + rh] = (uint32_t)v;
                            aL[cn][hf * 2 + rh] = (uint32_t)(v >> 32);
                        }
                    }

                float acc[4][4];
#pragma unroll
                for (int gb = 0; gb < 4; gb++)
#pragma unroll
                    for (int q = 0; q < 4; q++) acc[gb][q] = 0.f;

#pragma unroll
                for (int kt = 0; kt < 4; kt++) {
                    if (t == 0 && kt >= 2) continue;   // h = 0 at t=0
                    if (l == 0 && kt == 1) continue;   // x padded zeros
#pragma unroll
                    for (int gb = 0; gb < 4; gb++) {
                        hmma(acc[gb], aH[kt], bH[gb][kt]);
                        hmma(acc[gb], aH[kt], bL[gb][kt]);
                        hmma(acc[gb], aL[kt], bH[gb][kt]);
                    }
                }

                // ---- epilogue: 4 (e,j) pairs -> c,h; h re-enters fragments
#pragma unroll
                for (int rh = 0; rh < 2; rh++) {
                    float hp[2];
#pragma unroll
                    for (int p = 0; p < 2; p++) {
                        float gi = acc[0][rh * 2 + p] + bias[0][p];
                        float gf = acc[1][rh * 2 + p] + bias[1][p];
                        float gg = acc[2][rh * 2 + p] + bias[2][p];
                        float go = acc[3][rh * 2 + p] + bias[3][p];
                        float cc = sigf(gf) * cst[m][rh * 2 + p] + sigf(gi) * tanhfast(gg);
                        cst[m][rh * 2 + p] = cc;
                        hp[p] = sigf(go) * tanhfast(cc);
                    }
                    uint32_t vh, vl;
                    split2(hp[0], hp[1], vh, vl);
                    ull v = (ull)vh | ((ull)vl << 32);
                    int slot = ((w * 4 + m) * 2 + rh) * 32 + lane;
                    hx[(t + 1) & 1][slot] = v;
                    if (l < 4) {
                        xdst[(size_t)t * 1024 + slot] = v;
                    } else {
                        int e = e0 + 16 * m + r + 8 * rh;
                        size_t kb = (size_t)(stack * 640 + t * 32 + 8 * w + 2 * c);
                        d_fcT[kb * BB + e]       = hp[0];
                        d_fcT[(kb + 1) * BB + e] = hp[1];
                    }
                }
            }
        }
    }
}

// ---------------- FC head (unchanged, verified) ----------------
__global__ void transpose_w(const float* __restrict__ w) {
    int idx = blockIdx.x * 256 + threadIdx.x;
    int k = idx >> 7, o = idx & 127;
    d_wt[idx] = w[o * 1280 + k];
}

__device__ __forceinline__ ull pk2(float lo, float hi) {
    ull r; asm("mov.b64 %0, {%1, %2};" : "=l"(r) : "f"(lo), "f"(hi)); return r;
}
__device__ __forceinline__ void up2(ull v, float& lo, float& hi) {
    asm("mov.b64 {%0, %1}, %2;" : "=f"(lo), "=f"(hi) : "l"(v));
}
__device__ __forceinline__ ull fma2(ull a, ull b, ull c) {
    ull d; asm("fma.rn.f32x2 %0, %1, %2, %3;" : "=l"(d) : "l"(a), "l"(b), "l"(c)); return d;
}

__global__ void __launch_bounds__(256) fc_kernel(
    const float* __restrict__ fc1b, const float* __restrict__ fc2w,
    const float* __restrict__ fc2b, float* __restrict__ out) {
    __shared__ __align__(16) float As[16][64];
    __shared__ __align__(16) float Ws[16 * 128];
    __shared__ float H1[64][132];

    const int tid = threadIdx.x;
    const int b0 = blockIdx.x * 64;
    const int mi = tid & 15;
    const int ni = tid >> 4;

    ull acc[4][4];
#pragma unroll
    for (int i = 0; i < 4; i++)
#pragma unroll
        for (int p = 0; p < 4; p++) acc[i][p] = 0ull;

    const int akl = tid >> 4;
    const int ac4 = (tid & 15) * 4;

#pragma unroll 1
    for (int k0 = 0; k0 < 1280; k0 += 16) {
        __syncthreads();
        *(float4*)&As[akl][ac4] = *(const float4*)&d_fcT[(size_t)(k0 + akl) * BB + b0 + ac4];
        *(float4*)&Ws[tid * 4]        = *(const float4*)&d_wt[k0 * 128 + tid * 4];
        *(float4*)&Ws[1024 + tid * 4] = *(const float4*)&d_wt[k0 * 128 + 1024 + tid * 4];
        __syncthreads();
#pragma unroll
        for (int kl = 0; kl < 16; kl++) {
            float4 av = *(const float4*)&As[kl][mi * 4];
            ull ad0 = pk2(av.x, av.x), ad1 = pk2(av.y, av.y);
            ull ad2 = pk2(av.z, av.z), ad3 = pk2(av.w, av.w);
            const ulonglong2* wp = (const ulonglong2*)&Ws[kl * 128 + ni * 8];
            ulonglong2 w01 = wp[0], w23 = wp[1];
            acc[0][0] = fma2(ad0, w01.x, acc[0][0]); acc[0][1] = fma2(ad0, w01.y, acc[0][1]);
            acc[0][2] = fma2(ad0, w23.x, acc[0][2]); acc[0][3] = fma2(ad0, w23.y, acc[0][3]);
            acc[1][0] = fma2(ad1, w01.x, acc[1][0]); acc[1][1] = fma2(ad1, w01.y, acc[1][1]);
            acc[1][2] = fma2(ad1, w23.x, acc[1][2]); acc[1][3] = fma2(ad1, w23.y, acc[1][3]);
            acc[2][0] = fma2(ad2, w01.x, acc[2][0]); acc[2][1] = fma2(ad2, w01.y, acc[2][1]);
            acc[2][2] = fma2(ad2, w23.x, acc[2][2]); acc[2][3] = fma2(ad2, w23.y, acc[2][3]);
            acc[3][0] = fma2(ad3, w01.x, acc[3][0]); acc[3][1] = fma2(ad3, w01.y, acc[3][1]);
            acc[3][2] = fma2(ad3, w23.x, acc[3][2]); acc[3][3] = fma2(ad3, w23.y, acc[3][3]);
        }
    }
    __syncthreads();
#pragma unroll
    for (int i = 0; i < 4; i++) {
        int bl = mi * 4 + i;
#pragma unroll
        for (int p = 0; p < 4; p++) {
            int o = ni * 8 + 2 * p;
            float lo, hi; up2(acc[i][p], lo, hi);
            H1[bl][o]     = fmaxf(lo + fc1b[o], 0.f);
            H1[bl][o + 1] = fmaxf(hi + fc1b[o + 1], 0.f);
        }
    }
    __syncthreads();
    for (int idx = tid; idx < 320; idx += 256) {
        int bl = idx / 5, oo = idx - bl * 5;
        const float* w = fc2w + oo * 128;
        float s = fc2b[oo];
#pragma unroll 4
        for (int k = 0; k < 128; k++) s += H1[bl][k] * w[k];
        out[(size_t)(b0 + bl) * 5 + oo] = s;
    }
}

extern "C" void kernel_launch(void* const* d_in, const int* in_sizes, int n_in,
                              void* d_out, int out_size) {
    const float* accel = (const float*)d_in[0];
    const float* gyro  = (const float*)d_in[1];
    const float* aWih0 = (const float*)d_in[2];
    const float* aWihR = (const float*)d_in[3];
    const float* aWhh  = (const float*)d_in[4];
    const float* abih  = (const float*)d_in[5];
    const float* abhh  = (const float*)d_in[6];
    const float* gWih0 = (const float*)d_in[7];
    const float* gWihR = (const float*)d_in[8];
    const float* gWhh  = (const float*)d_in[9];
    const float* gbih  = (const float*)d_in[10];
    const float* gbhh  = (const float*)d_in[11];
    const float* fc1w  = (const float*)d_in[12];
    const float* fc1b  = (const float*)d_in[13];
    const float* fc2w  = (const float*)d_in[14];
    const float* fc2b  = (const float*)d_in[15];

    // lstm first so ncu -s capture lands on it
    lstm_mma_kernel<<<NCTA, 128>>>(accel, gyro, aWih0, aWihR, aWhh, abih, abhh,
                                   gWih0, gWihR, gWhh, gbih, gbhh);
    transpose_w<<<640, 256>>>(fc1w);
    fc_kernel<<<BB / 64, 256>>>(fc1b, fc2w, fc2b, (float*)d_out);
}